// round 2
// baseline (speedup 1.0000x reference)
#include <cuda_runtime.h>
#include <stdint.h>

#define BB 128
#define SS 512
#define HH 100
#define EE 300
#define CC 20

// Scratch (device globals: allocation-free per harness rules)
__device__ float d_X [SS*BB*EE];          // dropout(embedding), [s,b,e]   78.6 MB
__device__ float d_GI[SS*BB*EE];          // x @ w_ih^T + b_ih,  [s,b,3H]  78.6 MB
__device__ unsigned char d_m2[SS*BB*HH];  // dropout2 keep mask             6.6 MB

// ---------------------------------------------------------------------------
// JAX threefry2x32 (partitionable counter mode): bits(i) = o0 ^ o1 of
// E_{(k0,k1)}(x0=0, x1=i).  keep (bernoulli p=0.5) iff bits < 2^31.
// ---------------------------------------------------------------------------
__device__ __forceinline__ unsigned int tf_bits(unsigned int k0, unsigned int k1,
                                                unsigned int idx)
{
    unsigned int ks2 = k0 ^ k1 ^ 0x1BD11BDAu;
    unsigned int x0 = k0;         // 0 + ks0
    unsigned int x1 = idx + k1;   // i + ks1
#define TFR(r) { x0 += x1; x1 = __funnelshift_l(x1, x1, (r)); x1 ^= x0; }
    TFR(13) TFR(15) TFR(26) TFR(6)
    x0 += k1;  x1 += ks2 + 1u;
    TFR(17) TFR(29) TFR(16) TFR(24)
    x0 += ks2; x1 += k0 + 2u;
    TFR(13) TFR(15) TFR(26) TFR(6)
    x0 += k0;  x1 += k1 + 3u;
    TFR(17) TFR(29) TFR(16) TFR(24)
    x0 += k1;  x1 += ks2 + 4u;
    TFR(13) TFR(15) TFR(26) TFR(6)
    x0 += ks2; x1 += k0 + 5u;
#undef TFR
    return x0 ^ x1;
}

// ---------------------------------------------------------------------------
// K1: X[s,b,:] = where(m1, emb[tok[b,s]] * 2, 0)      (m1 flat over (B,S,E))
// ---------------------------------------------------------------------------
__global__ void k_embed(const int* __restrict__ inputs, const float* __restrict__ emb,
                        unsigned int k0, unsigned int k1)
{
    int row = blockIdx.x;               // row = s*128 + b
    int t   = threadIdx.x;
    if (t >= EE) return;
    int s = row >> 7;
    int b = row & 127;
    int tok = inputs[b*SS + s];
    unsigned int idx  = (unsigned int)((b*SS + s)*EE + t);   // (B,S,E) flat
    unsigned int bits = tf_bits(k0, k1, idx);
    float v = ((int)bits >= 0) ? 2.0f * emb[tok*EE + t] : 0.0f;
    d_X[row*EE + t] = v;
}

// ---------------------------------------------------------------------------
// K2: m2 keep mask over (S,B,H) flat
// ---------------------------------------------------------------------------
__global__ void k_m2(unsigned int k0, unsigned int k1)
{
    unsigned int idx = blockIdx.x * 256u + threadIdx.x;
    if (idx < (unsigned int)(SS*BB*HH))
        d_m2[idx] = (unsigned char)(((int)tf_bits(k0, k1, idx) >= 0) ? 1 : 0);
}

// ---------------------------------------------------------------------------
// K3: GI = X @ w_ih^T + b_ih     M=65536, N=300, K=300
// BM=128, BN=100, BK=15; 320 threads (tx 0..19 cols, ty 0..15 rows), 8x5 tile
// ---------------------------------------------------------------------------
__global__ __launch_bounds__(320, 2)
void k_gemm(const float* __restrict__ w_ih, const float* __restrict__ b_ih)
{
    __shared__ __align__(16) float Xs[15*132];   // [kk][m], padded stride 132
    __shared__ float Ws[15*102];                 // [kk][j], padded stride 102
    int j0   = blockIdx.x * 100;                 // 0..2   (fastest: L2 reuse of X)
    int row0 = blockIdx.y * 128;                 // 0..511
    int tid = threadIdx.x;
    int tx = tid % 20;
    int ty = tid / 20;

    float acc[8][5];
#pragma unroll
    for (int i = 0; i < 8; i++)
#pragma unroll
        for (int j = 0; j < 5; j++) acc[i][j] = 0.f;

    for (int k0 = 0; k0 < 300; k0 += 15) {
#pragma unroll
        for (int it = 0; it < 6; it++) {         // 1920 = 6*320 X elements
            int l = tid + it*320;
            int m = l / 15, kk = l - m*15;
            Xs[kk*132 + m] = d_X[(row0 + m)*300 + k0 + kk];
        }
#pragma unroll
        for (int it = 0; it < 5; it++) {         // 1500 W elements
            int l = tid + it*320;
            if (l < 1500) {
                int j = l / 15, kk = l - j*15;
                Ws[kk*102 + j] = w_ih[(j0 + j)*300 + k0 + kk];
            }
        }
        __syncthreads();
#pragma unroll
        for (int kk = 0; kk < 15; kk++) {
            float4 a0 = *reinterpret_cast<const float4*>(&Xs[kk*132 + ty*8]);
            float4 a1 = *reinterpret_cast<const float4*>(&Xs[kk*132 + ty*8 + 4]);
            float av[8] = {a0.x, a0.y, a0.z, a0.w, a1.x, a1.y, a1.z, a1.w};
            float bv[5];
#pragma unroll
            for (int j = 0; j < 5; j++) bv[j] = Ws[kk*102 + tx*5 + j];
#pragma unroll
            for (int i = 0; i < 8; i++)
#pragma unroll
                for (int j = 0; j < 5; j++)
                    acc[i][j] = fmaf(av[i], bv[j], acc[i][j]);
        }
        __syncthreads();
    }
#pragma unroll
    for (int j = 0; j < 5; j++) {
        float bias = b_ih[j0 + tx*5 + j];
#pragma unroll
        for (int i = 0; i < 8; i++)
            d_GI[(row0 + ty*8 + i)*300 + j0 + tx*5 + j] = acc[i][j] + bias;
    }
}

// ---------------------------------------------------------------------------
// K4: per-batch GRU recurrence + dropout2 + linear + log_softmax
// 128 CTAs (one per b), 352 threads:
//   t in [0,300)   : gh row t (w_hh row in registers), gates on t<100
//   warp 10 (t 320..351), lanes 0..19: logits/log_softmax of step s-1,
//   overlapped with step s's gh compute (double-buffered h_d).
// ---------------------------------------------------------------------------
__global__ __launch_bounds__(352, 1)
void k_recur(const float* __restrict__ w_hh, const float* __restrict__ b_hh,
             const float* __restrict__ w_lin, const float* __restrict__ b_lin,
             float* __restrict__ out)
{
    __shared__ __align__(16) float h_s[HH];
    __shared__ __align__(16) float hd_s[2][HH];
    __shared__ float gh_s[3*HH];
    __shared__ float gi_s[3*HH];

    int b = blockIdx.x;
    int t = threadIdx.x;
    int warp = t >> 5, lane = t & 31;

    float w[HH];                 // w_hh row t  OR  w_lin row (logits warp)
    float bias2 = 0.f;
    if (t < 300) {
#pragma unroll
        for (int k = 0; k < HH; k++) w[k] = w_hh[t*HH + k];
        bias2 = b_hh[t];
    } else if (warp == 10 && lane < CC) {
#pragma unroll
        for (int k = 0; k < HH; k++) w[k] = w_lin[lane*HH + k];
        bias2 = b_lin[lane];
    }

    if (t < HH) h_s[t] = 0.f;
    __syncthreads();

    float gi_cur = (t < 300) ? d_GI[b*300 + t] : 0.f;
    unsigned char m_cur = (t < HH) ? d_m2[b*HH + t] : (unsigned char)0;

    for (int s = 0; s < SS; s++) {
        // prefetch next step's gi row + mask (hides DRAM latency under compute)
        float gi_next = 0.f; unsigned char m_next = 0;
        if (s + 1 < SS) {
            if (t < 300) gi_next = d_GI[((s+1)*BB + b)*300 + t];
            if (t < HH)  m_next  = d_m2[((s+1)*BB + b)*HH + t];
        }

        if (t < 300) {
            gi_s[t] = gi_cur;
            float acc = bias2;
#pragma unroll
            for (int k = 0; k < HH; k += 4) {
                float4 h4 = *reinterpret_cast<const float4*>(&h_s[k]);
                acc = fmaf(w[k],   h4.x, acc);
                acc = fmaf(w[k+1], h4.y, acc);
                acc = fmaf(w[k+2], h4.z, acc);
                acc = fmaf(w[k+3], h4.w, acc);
            }
            gh_s[t] = acc;
        } else if (warp == 10 && s > 0) {
            // logits + log_softmax for step s-1 (overlapped with gh of step s)
            int sp = s - 1;
            int buf = sp & 1;
            float logit = __int_as_float(0xff800000);   // -inf for lanes >= 20
            if (lane < CC) {
                logit = bias2;
#pragma unroll
                for (int k = 0; k < HH; k += 4) {
                    float4 hv = *reinterpret_cast<const float4*>(&hd_s[buf][k]);
                    logit = fmaf(w[k],   hv.x, logit);
                    logit = fmaf(w[k+1], hv.y, logit);
                    logit = fmaf(w[k+2], hv.z, logit);
                    logit = fmaf(w[k+3], hv.w, logit);
                }
            }
            float mx = logit;
#pragma unroll
            for (int o = 16; o > 0; o >>= 1)
                mx = fmaxf(mx, __shfl_xor_sync(0xffffffffu, mx, o));
            float ex = (lane < CC) ? expf(logit - mx) : 0.f;
            float sm = ex;
#pragma unroll
            for (int o = 16; o > 0; o >>= 1)
                sm += __shfl_xor_sync(0xffffffffu, sm, o);
            if (lane < CC)
                out[(b*CC + lane)*SS + sp] = logit - mx - logf(sm);
        }
        __syncthreads();

        if (t < HH) {
            float r = 1.f / (1.f + expf(-(gi_s[t]      + gh_s[t])));
            float z = 1.f / (1.f + expf(-(gi_s[HH+t]   + gh_s[HH+t])));
            float n = tanhf(gi_s[2*HH+t] + r * gh_s[2*HH+t]);
            float hn = (1.f - z) * n + z * h_s[t];
            h_s[t] = hn;
            hd_s[s & 1][t] = m_cur ? 2.f * hn : 0.f;
        }
        __syncthreads();
        gi_cur = gi_next; m_cur = m_next;
    }

    // tail: logits for the last step (s = 511)
    if (warp == 10) {
        int sp = SS - 1;
        int buf = sp & 1;
        float logit = __int_as_float(0xff800000);
        if (lane < CC) {
            logit = bias2;
#pragma unroll
            for (int k = 0; k < HH; k += 4) {
                float4 hv = *reinterpret_cast<const float4*>(&hd_s[buf][k]);
                logit = fmaf(w[k],   hv.x, logit);
                logit = fmaf(w[k+1], hv.y, logit);
                logit = fmaf(w[k+2], hv.z, logit);
                logit = fmaf(w[k+3], hv.w, logit);
            }
        }
        float mx = logit;
#pragma unroll
        for (int o = 16; o > 0; o >>= 1)
            mx = fmaxf(mx, __shfl_xor_sync(0xffffffffu, mx, o));
        float ex = (lane < CC) ? expf(logit - mx) : 0.f;
        float sm = ex;
#pragma unroll
        for (int o = 16; o > 0; o >>= 1)
            sm += __shfl_xor_sync(0xffffffffu, sm, o);
        if (lane < CC)
            out[(b*CC + lane)*SS + sp] = logit - mx - logf(sm);
    }
}

// ---------------------------------------------------------------------------
// host-side threefry (pure arithmetic, graph-capture safe) for key derivation
// ---------------------------------------------------------------------------
static void tf_host(unsigned int k0, unsigned int k1, unsigned int x0i, unsigned int x1i,
                    unsigned int* o0, unsigned int* o1)
{
    unsigned int ks[3] = { k0, k1, k0 ^ k1 ^ 0x1BD11BDAu };
    const int rotA[4] = {13, 15, 26, 6}, rotB[4] = {17, 29, 16, 24};
    unsigned int x0 = x0i + ks[0], x1 = x1i + ks[1];
    for (int i = 0; i < 5; i++) {
        const int* r = (i & 1) ? rotB : rotA;
        for (int j = 0; j < 4; j++) {
            x0 += x1;
            x1 = (x1 << r[j]) | (x1 >> (32 - r[j]));
            x1 ^= x0;
        }
        x0 += ks[(i + 1) % 3];
        x1 += ks[(i + 2) % 3] + (unsigned int)(i + 1);
    }
    *o0 = x0; *o1 = x1;
}

extern "C" void kernel_launch(void* const* d_in, const int* in_sizes, int n_in,
                              void* d_out, int out_size)
{
    const int*   inputs = (const int*)  d_in[0];
    const float* emb    = (const float*)d_in[1];
    const float* w_ih   = (const float*)d_in[2];
    const float* w_hh   = (const float*)d_in[3];
    const float* b_ih   = (const float*)d_in[4];
    const float* b_hh   = (const float*)d_in[5];
    const float* w_lin  = (const float*)d_in[6];
    const float* b_lin  = (const float*)d_in[7];
    float* out = (float*)d_out;
    (void)in_sizes; (void)n_in; (void)out_size;

    // dk1, dk2 = split(key(42))  [fold-like / partitionable mode]
    unsigned int dk1_0, dk1_1, dk2_0, dk2_1;
    tf_host(0u, 42u, 0u, 0u, &dk1_0, &dk1_1);
    tf_host(0u, 42u, 0u, 1u, &dk2_0, &dk2_1);

    k_embed<<<SS*BB, 320>>>(inputs, emb, dk1_0, dk1_1);
    k_m2<<<(SS*BB*HH + 255)/256, 256>>>(dk2_0, dk2_1);
    k_gemm<<<dim3(3, 512), 320>>>(w_ih, b_ih);
    k_recur<<<BB, 352>>>(w_hh, b_hh, w_lin, b_lin, out);
}

// round 6
// speedup vs baseline: 1.0998x; 1.0998x over previous
#include <cuda_runtime.h>
#include <stdint.h>

#define BB 128
#define SS 512
#define HH 100
#define EE 300
#define CC 20

typedef unsigned long long ull;

// Scratch (device globals: allocation-free per harness rules)
__device__ float d_X [SS*BB*EE];          // dropout(embedding), [s,b,e]
__device__ float d_GI[SS*BB*EE];          // x @ w_ih^T + b_ih,  [s,b,3H]
__device__ unsigned char d_m2[SS*BB*HH];  // dropout2 keep mask

// ---------------------------------------------------------------------------
// f32x2 packed-math helpers (Blackwell FFMA2) — IEEE-identical rounding to FFMA
// ---------------------------------------------------------------------------
__device__ __forceinline__ ull fma2(ull a, ull b, ull c) {
    ull d;
    asm("fma.rn.f32x2 %0, %1, %2, %3;" : "=l"(d) : "l"(a), "l"(b), "l"(c));
    return d;
}
__device__ __forceinline__ ull pack2(float lo, float hi) {
    ull r; asm("mov.b64 %0, {%1,%2};" : "=l"(r) : "f"(lo), "f"(hi)); return r;
}
__device__ __forceinline__ float2 unpack2(ull v) {
    float lo, hi; asm("mov.b64 {%0,%1}, %2;" : "=f"(lo), "=f"(hi) : "l"(v));
    return make_float2(lo, hi);
}

// ---------------------------------------------------------------------------
// JAX threefry2x32 (partitionable counter mode): bits(i) = o0 ^ o1 of
// E_{(k0,k1)}(x0=0, x1=i).  keep (bernoulli p=0.5) iff bits < 2^31.
// ---------------------------------------------------------------------------
__device__ __forceinline__ unsigned int tf_bits(unsigned int k0, unsigned int k1,
                                                unsigned int idx)
{
    unsigned int ks2 = k0 ^ k1 ^ 0x1BD11BDAu;
    unsigned int x0 = k0;
    unsigned int x1 = idx + k1;
#define TFR(r) { x0 += x1; x1 = __funnelshift_l(x1, x1, (r)); x1 ^= x0; }
    TFR(13) TFR(15) TFR(26) TFR(6)
    x0 += k1;  x1 += ks2 + 1u;
    TFR(17) TFR(29) TFR(16) TFR(24)
    x0 += ks2; x1 += k0 + 2u;
    TFR(13) TFR(15) TFR(26) TFR(6)
    x0 += k0;  x1 += k1 + 3u;
    TFR(17) TFR(29) TFR(16) TFR(24)
    x0 += k1;  x1 += ks2 + 4u;
    TFR(13) TFR(15) TFR(26) TFR(6)
    x0 += ks2; x1 += k0 + 5u;
#undef TFR
    return x0 ^ x1;
}

// ---------------------------------------------------------------------------
// K1: X[s,b,:] = where(m1, emb[tok[b,s]] * 2, 0)
// ---------------------------------------------------------------------------
__global__ void k_embed(const int* __restrict__ inputs, const float* __restrict__ emb,
                        unsigned int k0, unsigned int k1)
{
    int row = blockIdx.x;               // row = s*128 + b
    int t   = threadIdx.x;
    if (t >= EE) return;
    int s = row >> 7;
    int b = row & 127;
    int tok = inputs[b*SS + s];
    unsigned int idx  = (unsigned int)((b*SS + s)*EE + t);   // (B,S,E) flat
    unsigned int bits = tf_bits(k0, k1, idx);
    float v = ((int)bits >= 0) ? 2.0f * emb[tok*EE + t] : 0.0f;
    d_X[row*EE + t] = v;
}

// ---------------------------------------------------------------------------
// K2: m2 keep mask over (S,B,H) flat
// ---------------------------------------------------------------------------
__global__ void k_m2(unsigned int k0, unsigned int k1)
{
    unsigned int idx = blockIdx.x * 256u + threadIdx.x;
    if (idx < (unsigned int)(SS*BB*HH))
        d_m2[idx] = (unsigned char)(((int)tf_bits(k0, k1, idx) >= 0) ? 1 : 0);
}

// ---------------------------------------------------------------------------
// K3: GI = X @ w_ih^T + b_ih     M=65536, N=300, K=300
// BM=128, BN=100, BK=15; 320 threads; 8x5 register tile done as
// 4 row-pair f32x2 accumulators x 5 cols.  Per-element summation order is
// identical to a serial FFMA chain (packing is across rows).
// ---------------------------------------------------------------------------
__global__ __launch_bounds__(320, 2)
void k_gemm(const float* __restrict__ w_ih, const float* __restrict__ b_ih)
{
    __shared__ __align__(16) float Xs[15*132];   // [kk][m], padded stride 132
    __shared__ float Ws[15*102];                 // [kk][j], padded stride 102
    int j0   = blockIdx.x * 100;
    int row0 = blockIdx.y * 128;
    int tid = threadIdx.x;
    int tx = tid % 20;
    int ty = tid / 20;

    ull acc[4][5];
#pragma unroll
    for (int i = 0; i < 4; i++)
#pragma unroll
        for (int j = 0; j < 5; j++) acc[i][j] = 0ull;

    for (int k0 = 0; k0 < 300; k0 += 15) {
#pragma unroll
        for (int it = 0; it < 6; it++) {
            int l = tid + it*320;
            int m = l / 15, kk = l - m*15;
            Xs[kk*132 + m] = d_X[(row0 + m)*300 + k0 + kk];
        }
#pragma unroll
        for (int it = 0; it < 5; it++) {
            int l = tid + it*320;
            if (l < 1500) {
                int j = l / 15, kk = l - j*15;
                Ws[kk*102 + j] = w_ih[(j0 + j)*300 + k0 + kk];
            }
        }
        __syncthreads();
#pragma unroll
        for (int kk = 0; kk < 15; kk++) {
            const ull* xp = reinterpret_cast<const ull*>(&Xs[kk*132 + ty*8]);
            ull av[4];
#pragma unroll
            for (int i = 0; i < 4; i++) av[i] = xp[i];
            ull bv[5];
#pragma unroll
            for (int j = 0; j < 5; j++) {
                float b = Ws[kk*102 + tx*5 + j];
                bv[j] = pack2(b, b);
            }
#pragma unroll
            for (int i = 0; i < 4; i++)
#pragma unroll
                for (int j = 0; j < 5; j++)
                    acc[i][j] = fma2(av[i], bv[j], acc[i][j]);
        }
        __syncthreads();
    }
#pragma unroll
    for (int j = 0; j < 5; j++) {
        float bias = b_ih[j0 + tx*5 + j];
#pragma unroll
        for (int i = 0; i < 4; i++) {
            float2 v = unpack2(acc[i][j]);
            d_GI[(row0 + ty*8 + 2*i    )*300 + j0 + tx*5 + j] = v.x + bias;
            d_GI[(row0 + ty*8 + 2*i + 1)*300 + j0 + tx*5 + j] = v.y + bias;
        }
    }
}

// accurate sigmoid (libm expf — numerics proven in R2)
__device__ __forceinline__ float sigmoidf_acc(float x) {
    return 1.0f / (1.0f + expf(-x));
}

// ---------------------------------------------------------------------------
// K4: per-batch GRU recurrence + dropout2 + linear + log_softmax
// 128 CTAs (one per b), 352 threads:
//   phase1: t in [0,300): gh row t via f32x2 dot (LDS.128 h loads);
//           t<100 fold sigmoid(r), t in [100,200) fold sigmoid(z) right after
//           their own dot (parallel across warps, overlapped with other dots);
//           warp 10 lanes 0..19: logits/log_softmax of step s-1.
//   phase2: t<100: n = tanhf(gi_n + r*gh_n); h update; dropout2.
// ---------------------------------------------------------------------------
__global__ __launch_bounds__(352, 1)
void k_recur(const float* __restrict__ w_hh, const float* __restrict__ b_hh,
             const float* __restrict__ w_lin, const float* __restrict__ b_lin,
             float* __restrict__ out)
{
    __shared__ __align__(16) float h_s[HH];
    __shared__ __align__(16) float hd_s[2][HH];
    __shared__ float rz_s[2*HH];     // [0,100)=r, [100,200)=z
    __shared__ float ghn_s[HH];      // gh of n rows
    __shared__ float gin_s[HH];      // gi of n rows

    int b = blockIdx.x;
    int t = threadIdx.x;
    int warp = t >> 5, lane = t & 31;

    ull w2[50];                  // packed w_hh row t  OR  w_lin row (logits warp)
    float bias2 = 0.f;
    if (t < 300) {
        const ull* wp = reinterpret_cast<const ull*>(w_hh + t*HH);
#pragma unroll
        for (int k = 0; k < 50; k++) w2[k] = wp[k];
        bias2 = b_hh[t];
    } else if (warp == 10 && lane < CC) {
        const ull* wp = reinterpret_cast<const ull*>(w_lin + lane*HH);
#pragma unroll
        for (int k = 0; k < 50; k++) w2[k] = wp[k];
        bias2 = b_lin[lane];
    }

    if (t < HH) h_s[t] = 0.f;
    __syncthreads();

    const bool is_dot  = (t < 300);
    const bool is_gate = (t < HH);

    float gi_cur = is_dot ? d_GI[b*300 + t] : 0.f;
    unsigned char m_cur = is_gate ? d_m2[b*HH + t] : (unsigned char)0;

    for (int s = 0; s < SS; s++) {
        // prefetch next step's gi row + mask — issued up-front so the LDGs are
        // in flight while the dot below runs (hides DRAM latency)
        float gi_next = 0.f; unsigned char m_next = 0;
        if (s + 1 < SS) {
            if (is_dot)  gi_next = __ldg(&d_GI[((s+1)*BB + b)*300 + t]);
            if (is_gate) m_next  = __ldg(&d_m2[((s+1)*BB + b)*HH + t]);
        }

        if (is_dot) {
            const ulonglong2* hp = reinterpret_cast<const ulonglong2*>(h_s);
            ull a0 = pack2(bias2, 0.f), a1 = 0ull, a2 = 0ull, a3 = 0ull;
#pragma unroll
            for (int k = 0; k < 24; k += 2) {       // 48 pairs
                ulonglong2 hA = hp[k], hB = hp[k+1];
                a0 = fma2(w2[2*k    ], hA.x, a0);
                a1 = fma2(w2[2*k + 1], hA.y, a1);
                a2 = fma2(w2[2*k + 2], hB.x, a2);
                a3 = fma2(w2[2*k + 3], hB.y, a3);
            }
            {                                        // last 2 pairs (48,49)
                ulonglong2 hA = hp[24];
                a0 = fma2(w2[48], hA.x, a0);
                a1 = fma2(w2[49], hA.y, a1);
            }
            float2 f0 = unpack2(a0), f1 = unpack2(a1);
            float2 f2 = unpack2(a2), f3 = unpack2(a3);
            float gh = ((f0.x + f0.y) + (f1.x + f1.y)) +
                       ((f2.x + f2.y) + (f3.x + f3.y));
            if (t < 2*HH) {
                // r / z rows: fold the sigmoid here (overlapped across warps)
                rz_s[t] = sigmoidf_acc(gi_cur + gh);
            } else {
                ghn_s[t - 2*HH] = gh;
                gin_s[t - 2*HH] = gi_cur;
            }
        } else if (warp == 10 && s > 0) {
            // logits + log_softmax for step s-1 (overlapped with phase1 of s)
            int sp = s - 1;
            int buf = sp & 1;
            float logit = __int_as_float(0xff800000);
            if (lane < CC) {
                const ulonglong2* hp = reinterpret_cast<const ulonglong2*>(hd_s[buf]);
                ull a0 = pack2(bias2, 0.f), a1 = 0ull;
#pragma unroll
                for (int k = 0; k < 25; k++) {
                    ulonglong2 hv = hp[k];
                    a0 = fma2(w2[2*k    ], hv.x, a0);
                    a1 = fma2(w2[2*k + 1], hv.y, a1);
                }
                float2 f0 = unpack2(a0), f1 = unpack2(a1);
                logit = (f0.x + f0.y) + (f1.x + f1.y);
            }
            float mx = logit;
#pragma unroll
            for (int o = 16; o > 0; o >>= 1)
                mx = fmaxf(mx, __shfl_xor_sync(0xffffffffu, mx, o));
            float ex = (lane < CC) ? expf(logit - mx) : 0.f;
            float sm = ex;
#pragma unroll
            for (int o = 16; o > 0; o >>= 1)
                sm += __shfl_xor_sync(0xffffffffu, sm, o);
            if (lane < CC)
                out[(b*CC + lane)*SS + sp] = logit - mx - logf(sm);
        }
        __syncthreads();

        if (is_gate) {
            float r = rz_s[t];
            float z = rz_s[HH + t];
            float n = tanhf(gin_s[t] + r * ghn_s[t]);
            float hn = (1.f - z) * n + z * h_s[t];
            h_s[t] = hn;
            hd_s[s & 1][t] = m_cur ? 2.f * hn : 0.f;
        }
        __syncthreads();
        gi_cur = gi_next; m_cur = m_next;
    }

    // tail: logits for the last step (s = 511)
    if (warp == 10) {
        int sp = SS - 1;
        int buf = sp & 1;
        float logit = __int_as_float(0xff800000);
        if (lane < CC) {
            const ulonglong2* hp = reinterpret_cast<const ulonglong2*>(hd_s[buf]);
            ull a0 = pack2(bias2, 0.f), a1 = 0ull;
#pragma unroll
            for (int k = 0; k < 25; k++) {
                ulonglong2 hv = hp[k];
                a0 = fma2(w2[2*k    ], hv.x, a0);
                a1 = fma2(w2[2*k + 1], hv.y, a1);
            }
            float2 f0 = unpack2(a0), f1 = unpack2(a1);
            logit = (f0.x + f0.y) + (f1.x + f1.y);
        }
        float mx = logit;
#pragma unroll
        for (int o = 16; o > 0; o >>= 1)
            mx = fmaxf(mx, __shfl_xor_sync(0xffffffffu, mx, o));
        float ex = (lane < CC) ? expf(logit - mx) : 0.f;
        float sm = ex;
#pragma unroll
        for (int o = 16; o > 0; o >>= 1)
            sm += __shfl_xor_sync(0xffffffffu, sm, o);
        if (lane < CC)
            out[(b*CC + lane)*SS + sp] = logit - mx - logf(sm);
    }
}

// ---------------------------------------------------------------------------
// host-side threefry for key derivation
// ---------------------------------------------------------------------------
static void tf_host(unsigned int k0, unsigned int k1, unsigned int x0i, unsigned int x1i,
                    unsigned int* o0, unsigned int* o1)
{
    unsigned int ks[3] = { k0, k1, k0 ^ k1 ^ 0x1BD11BDAu };
    const int rotA[4] = {13, 15, 26, 6}, rotB[4] = {17, 29, 16, 24};
    unsigned int x0 = x0i + ks[0], x1 = x1i + ks[1];
    for (int i = 0; i < 5; i++) {
        const int* r = (i & 1) ? rotB : rotA;
        for (int j = 0; j < 4; j++) {
            x0 += x1;
            x1 = (x1 << r[j]) | (x1 >> (32 - r[j]));
            x1 ^= x0;
        }
        x0 += ks[(i + 1) % 3];
        x1 += ks[(i + 2) % 3] + (unsigned int)(i + 1);
    }
    *o0 = x0; *o1 = x1;
}

extern "C" void kernel_launch(void* const* d_in, const int* in_sizes, int n_in,
                              void* d_out, int out_size)
{
    const int*   inputs = (const int*)  d_in[0];
    const float* emb    = (const float*)d_in[1];
    const float* w_ih   = (const float*)d_in[2];
    const float* w_hh   = (const float*)d_in[3];
    const float* b_ih   = (const float*)d_in[4];
    const float* b_hh   = (const float*)d_in[5];
    const float* w_lin  = (const float*)d_in[6];
    const float* b_lin  = (const float*)d_in[7];
    float* out = (float*)d_out;
    (void)in_sizes; (void)n_in; (void)out_size;

    unsigned int dk1_0, dk1_1, dk2_0, dk2_1;
    tf_host(0u, 42u, 0u, 0u, &dk1_0, &dk1_1);
    tf_host(0u, 42u, 0u, 1u, &dk2_0, &dk2_1);

    k_embed<<<SS*BB, 320>>>(inputs, emb, dk1_0, dk1_1);
    k_m2<<<(SS*BB*HH + 255)/256, 256>>>(dk2_0, dk2_1);
    k_gemm<<<dim3(3, 512), 320>>>(w_ih, b_ih);
    k_recur<<<BB, 352>>>(w_hh, b_hh, w_lin, b_lin, out);
}